// round 1
// baseline (speedup 1.0000x reference)
#include <cuda_runtime.h>
#include <math.h>

#define NRES 8192
#define NK   48
#define NH   128

// Scratch (device globals: no allocation allowed in kernel_launch)
__device__ float g_Pi[NRES * NH];   // node_h @ W1a
__device__ float g_Pj[NRES * NH];   // node_h @ W1b
__device__ float g_Ps[NRES * NH];   // seq_emb @ W1d
__device__ float g_agg[NRES * NH];  // sum_k msg

__device__ __forceinline__ float gelu_exact(float x) {
    return 0.5f * x * (1.0f + erff(x * 0.7071067811865475f));
}

// ---------------------------------------------------------------------------
// Kernel 1: precompute the three per-residue projections of mW1.
//   which==0: g_Pi = node_h @ mW1[0:128]
//   which==1: g_Pj = node_h @ mW1[128:256]
//   which==2: g_Ps = seq_emb @ mW1[384:512]
// Tile M=64, N=128, K=128. 256 threads, 4x8 accumulators/thread.
// ---------------------------------------------------------------------------
__global__ __launch_bounds__(256) void k1_pre(const float* __restrict__ node_h,
                                              const float* __restrict__ seq_emb,
                                              const float* __restrict__ mW1) {
    extern __shared__ float sm1[];
    float* Wsh = sm1;            // 128*128
    float* Ash = sm1 + 16384;    // 64*132 (padded rows)

    const int tid   = threadIdx.x;
    const int which = blockIdx.y;
    const float* A    = (which == 2) ? seq_emb : node_h;
    const float* Wsrc = mW1 + (size_t)(which == 0 ? 0 : (which == 1 ? 128 : 384)) * NH;
    float* out = (which == 0) ? g_Pi : (which == 1 ? g_Pj : g_Ps);

    for (int i = tid; i < 4096; i += 256)
        ((float4*)Wsh)[i] = ((const float4*)Wsrc)[i];

    const int m0 = blockIdx.x * 64;
    for (int i = tid; i < 64 * 32; i += 256) {
        int r = i >> 5, c4 = i & 31;
        *(float4*)&Ash[r * 132 + c4 * 4] = ((const float4*)(A + (size_t)(m0 + r) * NH))[c4];
    }
    __syncthreads();

    const int tc = tid & 15, tr = tid >> 4;
    float acc[4][8];
#pragma unroll
    for (int i = 0; i < 4; i++)
#pragma unroll
        for (int j = 0; j < 8; j++) acc[i][j] = 0.f;

#pragma unroll 4
    for (int kk = 0; kk < 128; kk++) {
        float4 b0 = *(const float4*)&Wsh[kk * 128 + tc * 8];
        float4 b1 = *(const float4*)&Wsh[kk * 128 + tc * 8 + 4];
#pragma unroll
        for (int i = 0; i < 4; i++) {
            float a = Ash[(tr * 4 + i) * 132 + kk];
            acc[i][0] = fmaf(a, b0.x, acc[i][0]);
            acc[i][1] = fmaf(a, b0.y, acc[i][1]);
            acc[i][2] = fmaf(a, b0.z, acc[i][2]);
            acc[i][3] = fmaf(a, b0.w, acc[i][3]);
            acc[i][4] = fmaf(a, b1.x, acc[i][4]);
            acc[i][5] = fmaf(a, b1.y, acc[i][5]);
            acc[i][6] = fmaf(a, b1.z, acc[i][6]);
            acc[i][7] = fmaf(a, b1.w, acc[i][7]);
        }
    }
#pragma unroll
    for (int i = 0; i < 4; i++) {
        size_t r = (size_t)(m0 + tr * 4 + i) * NH + tc * 8;
#pragma unroll
        for (int j = 0; j < 8; j++) out[r + j] = acc[i][j];
    }
}

// ---------------------------------------------------------------------------
// Kernel 2: per-edge message MLP, fused + aggregated.
// Persistent: each CTA processes residue PAIRS (96 edge rows) in a stride loop.
// Per pair:
//   X1 = gelu(E @ W1c + Pi[res] + Pj[nbr] + am*Ps[nbr] + mb1)   [96 x 128]
//   X2 = gelu(X1 @ W2 + mb2)                                    [96 x 128]
//   s[res] = sum over 48 rows of X2
//   agg[res] = s @ W3 + 48*mb3        (GEMV: sum-before-GEMM3 identity)
// Weights W1c/W2 resident in SMEM; activations in SMEM; accumulators in regs.
// ---------------------------------------------------------------------------
__global__ __launch_bounds__(256) void k2_msg(const float* __restrict__ edge_h,
                                              const int*   __restrict__ edge_idx,
                                              const float* __restrict__ ar_mask,
                                              const float* __restrict__ mW1,
                                              const float* __restrict__ mb1,
                                              const float* __restrict__ mW2,
                                              const float* __restrict__ mb2,
                                              const float* __restrict__ mW3,
                                              const float* __restrict__ mb3,
                                              int npairs) {
    extern __shared__ float sm2[];
    float* W1sh = sm2;              // 128*128   (W1c = mW1 rows 256..383)
    float* W2sh = sm2 + 16384;      // 128*128
    float* Bsh  = sm2 + 32768;      // 96*132 activation buffer (padded)
    float* Ssh  = sm2 + 32768 + 96 * 132;  // 2*128 column sums
    __shared__ int   idx_sh[96];
    __shared__ float am_sh[96];

    const int tid = threadIdx.x;
    for (int i = tid; i < 4096; i += 256) {
        ((float4*)W1sh)[i] = ((const float4*)(mW1 + 256 * NH))[i];
        ((float4*)W2sh)[i] = ((const float4*)mW2)[i];
    }

    const int tc = tid & 15, tr = tid >> 4;

    for (int p = blockIdx.x; p < npairs; p += gridDim.x) {
        __syncthreads();  // separate from previous iteration's reads
        const int r0 = p * 2;
        if (tid < 96) {
            idx_sh[tid] = edge_idx[(size_t)r0 * NK + tid];
            am_sh[tid]  = ar_mask[(size_t)r0 * NK + tid];
        }
        // load edge tile: 96 rows x 128 cols (contiguous for the 2 residues)
        const float4* Esrc = (const float4*)(edge_h + (size_t)r0 * NK * NH);
        for (int i = tid; i < 96 * 32; i += 256) {
            int r = i >> 5, c4 = i & 31;
            *(float4*)&Bsh[r * 132 + c4 * 4] = Esrc[i];
        }
        __syncthreads();

        // ---- GEMM1: acc = base + E @ W1c ----
        float acc[6][8];
#pragma unroll
        for (int i = 0; i < 6; i++) {
            int r   = tr * 6 + i;
            int res = r0 + (r >= 48 ? 1 : 0);
            int nbr = idx_sh[r];
            float amv = am_sh[r];
            const float4* pi = (const float4*)(g_Pi + (size_t)res * NH + tc * 8);
            const float4* pj = (const float4*)(g_Pj + (size_t)nbr * NH + tc * 8);
            const float4* ps = (const float4*)(g_Ps + (size_t)nbr * NH + tc * 8);
            const float4* bb = (const float4*)(mb1 + tc * 8);
#pragma unroll
            for (int h = 0; h < 2; h++) {
                float4 A = pi[h], B = pj[h], C = ps[h], D = bb[h];
                acc[i][h * 4 + 0] = A.x + B.x + amv * C.x + D.x;
                acc[i][h * 4 + 1] = A.y + B.y + amv * C.y + D.y;
                acc[i][h * 4 + 2] = A.z + B.z + amv * C.z + D.z;
                acc[i][h * 4 + 3] = A.w + B.w + amv * C.w + D.w;
            }
        }
#pragma unroll 4
        for (int kk = 0; kk < 128; kk++) {
            float4 b0 = *(const float4*)&W1sh[kk * 128 + tc * 8];
            float4 b1 = *(const float4*)&W1sh[kk * 128 + tc * 8 + 4];
#pragma unroll
            for (int i = 0; i < 6; i++) {
                float a = Bsh[(tr * 6 + i) * 132 + kk];
                acc[i][0] = fmaf(a, b0.x, acc[i][0]);
                acc[i][1] = fmaf(a, b0.y, acc[i][1]);
                acc[i][2] = fmaf(a, b0.z, acc[i][2]);
                acc[i][3] = fmaf(a, b0.w, acc[i][3]);
                acc[i][4] = fmaf(a, b1.x, acc[i][4]);
                acc[i][5] = fmaf(a, b1.y, acc[i][5]);
                acc[i][6] = fmaf(a, b1.z, acc[i][6]);
                acc[i][7] = fmaf(a, b1.w, acc[i][7]);
            }
        }
        // gelu, write X1 back
#pragma unroll
        for (int i = 0; i < 6; i++)
#pragma unroll
            for (int j = 0; j < 8; j++) acc[i][j] = gelu_exact(acc[i][j]);
        __syncthreads();
#pragma unroll
        for (int i = 0; i < 6; i++)
#pragma unroll
            for (int j = 0; j < 8; j++) Bsh[(tr * 6 + i) * 132 + tc * 8 + j] = acc[i][j];
        __syncthreads();

        // ---- GEMM2: acc = mb2 + X1 @ W2 ----
#pragma unroll
        for (int i = 0; i < 6; i++)
#pragma unroll
            for (int j = 0; j < 8; j++) acc[i][j] = mb2[tc * 8 + j];
#pragma unroll 4
        for (int kk = 0; kk < 128; kk++) {
            float4 b0 = *(const float4*)&W2sh[kk * 128 + tc * 8];
            float4 b1 = *(const float4*)&W2sh[kk * 128 + tc * 8 + 4];
#pragma unroll
            for (int i = 0; i < 6; i++) {
                float a = Bsh[(tr * 6 + i) * 132 + kk];
                acc[i][0] = fmaf(a, b0.x, acc[i][0]);
                acc[i][1] = fmaf(a, b0.y, acc[i][1]);
                acc[i][2] = fmaf(a, b0.z, acc[i][2]);
                acc[i][3] = fmaf(a, b0.w, acc[i][3]);
                acc[i][4] = fmaf(a, b1.x, acc[i][4]);
                acc[i][5] = fmaf(a, b1.y, acc[i][5]);
                acc[i][6] = fmaf(a, b1.z, acc[i][6]);
                acc[i][7] = fmaf(a, b1.w, acc[i][7]);
            }
        }
#pragma unroll
        for (int i = 0; i < 6; i++)
#pragma unroll
            for (int j = 0; j < 8; j++) acc[i][j] = gelu_exact(acc[i][j]);
        __syncthreads();
#pragma unroll
        for (int i = 0; i < 6; i++)
#pragma unroll
            for (int j = 0; j < 8; j++) Bsh[(tr * 6 + i) * 132 + tc * 8 + j] = acc[i][j];
        __syncthreads();

        // ---- column sums over K=48 rows per residue ----
        {
            int res_l = tid >> 7;      // 0..1
            int col   = tid & 127;
            float s = 0.f;
#pragma unroll 8
            for (int k = 0; k < 48; k++) s += Bsh[(res_l * 48 + k) * 132 + col];
            Ssh[res_l * 128 + col] = s;
        }
        __syncthreads();

        // ---- GEMV: agg = s @ W3 + 48*mb3 ----
        {
            int res_l = tid >> 7;
            int col   = tid & 127;
            const float* srow = &Ssh[res_l * 128];
            float v = 48.f * mb3[col];
#pragma unroll 8
            for (int k = 0; k < 128; k++) v = fmaf(srow[k], mW3[k * 128 + col], v);
            g_agg[(size_t)(r0 + res_l) * NH + col] = v;
        }
    }
}

// ---------------------------------------------------------------------------
// Kernel 3: h = LN1(node_h + agg); out = LN2(h + FFN(h))
// 32 residues per CTA, FFN weights streamed in 128-col/row chunks.
// ---------------------------------------------------------------------------
__global__ __launch_bounds__(256) void k3_ff(const float* __restrict__ node_h,
                                             const float* __restrict__ fW1,
                                             const float* __restrict__ fb1,
                                             const float* __restrict__ fW2,
                                             const float* __restrict__ fb2,
                                             const float* __restrict__ g1,
                                             const float* __restrict__ b1,
                                             const float* __restrict__ g2,
                                             const float* __restrict__ b2,
                                             float* __restrict__ out) {
    extern __shared__ float sm3[];
    float* H1sh = sm3;                 // 32*132
    float* Tsh  = sm3 + 32 * 132;      // 32*516
    float* Wsh  = sm3 + 32 * 132 + 32 * 516;  // 128*128

    const int tid  = threadIdx.x;
    const int wid  = tid >> 5, lane = tid & 31;
    const int m0   = blockIdx.x * 32;

    // step 1: u = node_h + agg; LN1 -> H1sh
    for (int r = wid; r < 32; r += 8) {
        const int c0 = lane * 4;
        float4 a = *(const float4*)&node_h[(size_t)(m0 + r) * NH + c0];
        float4 g = *(const float4*)&g_agg[(size_t)(m0 + r) * NH + c0];
        float v0 = a.x + g.x, v1 = a.y + g.y, v2 = a.z + g.z, v3 = a.w + g.w;
        float s = v0 + v1 + v2 + v3;
#pragma unroll
        for (int o = 16; o; o >>= 1) s += __shfl_xor_sync(0xffffffffu, s, o);
        float mu = s * (1.f / 128.f);
        float d0 = v0 - mu, d1 = v1 - mu, d2 = v2 - mu, d3 = v3 - mu;
        float q = d0 * d0 + d1 * d1 + d2 * d2 + d3 * d3;
#pragma unroll
        for (int o = 16; o; o >>= 1) q += __shfl_xor_sync(0xffffffffu, q, o);
        float rs = rsqrtf(q * (1.f / 128.f) + 1e-5f);
        H1sh[r * 132 + c0 + 0] = d0 * rs * g1[c0 + 0] + b1[c0 + 0];
        H1sh[r * 132 + c0 + 1] = d1 * rs * g1[c0 + 1] + b1[c0 + 1];
        H1sh[r * 132 + c0 + 2] = d2 * rs * g1[c0 + 2] + b1[c0 + 2];
        H1sh[r * 132 + c0 + 3] = d3 * rs * g1[c0 + 3] + b1[c0 + 3];
    }

    const int tc = tid & 15, tr = tid >> 4;

    // step 2: FF1 (128 -> 512) in 4 column chunks, gelu -> Tsh
    for (int nc = 0; nc < 4; nc++) {
        __syncthreads();
        for (int i = tid; i < 4096; i += 256) {
            int k = i >> 5, c4 = i & 31;
            ((float4*)&Wsh[k * 128])[c4] = ((const float4*)&fW1[(size_t)k * 512 + nc * 128])[c4];
        }
        __syncthreads();
        float acc[2][8];
#pragma unroll
        for (int i = 0; i < 2; i++)
#pragma unroll
            for (int j = 0; j < 8; j++) acc[i][j] = fb1[nc * 128 + tc * 8 + j];
#pragma unroll 4
        for (int kk = 0; kk < 128; kk++) {
            float4 b0 = *(const float4*)&Wsh[kk * 128 + tc * 8];
            float4 b1v = *(const float4*)&Wsh[kk * 128 + tc * 8 + 4];
#pragma unroll
            for (int i = 0; i < 2; i++) {
                float a = H1sh[(tr * 2 + i) * 132 + kk];
                acc[i][0] = fmaf(a, b0.x, acc[i][0]);
                acc[i][1] = fmaf(a, b0.y, acc[i][1]);
                acc[i][2] = fmaf(a, b0.z, acc[i][2]);
                acc[i][3] = fmaf(a, b0.w, acc[i][3]);
                acc[i][4] = fmaf(a, b1v.x, acc[i][4]);
                acc[i][5] = fmaf(a, b1v.y, acc[i][5]);
                acc[i][6] = fmaf(a, b1v.z, acc[i][6]);
                acc[i][7] = fmaf(a, b1v.w, acc[i][7]);
            }
        }
#pragma unroll
        for (int i = 0; i < 2; i++)
#pragma unroll
            for (int j = 0; j < 8; j++)
                Tsh[(tr * 2 + i) * 516 + nc * 128 + tc * 8 + j] = gelu_exact(acc[i][j]);
    }

    // step 3: FF2 (512 -> 128), K streamed in 4 chunks
    float acc2[2][8];
#pragma unroll
    for (int i = 0; i < 2; i++)
#pragma unroll
        for (int j = 0; j < 8; j++) acc2[i][j] = fb2[tc * 8 + j];
    for (int kc = 0; kc < 4; kc++) {
        __syncthreads();
        for (int i = tid; i < 4096; i += 256) {
            int k = i >> 5, c4 = i & 31;
            ((float4*)&Wsh[k * 128])[c4] = ((const float4*)&fW2[(size_t)(kc * 128 + k) * 128])[c4];
        }
        __syncthreads();
#pragma unroll 4
        for (int kk = 0; kk < 128; kk++) {
            float4 b0 = *(const float4*)&Wsh[kk * 128 + tc * 8];
            float4 b1v = *(const float4*)&Wsh[kk * 128 + tc * 8 + 4];
#pragma unroll
            for (int i = 0; i < 2; i++) {
                float a = Tsh[(tr * 2 + i) * 516 + kc * 128 + kk];
                acc2[i][0] = fmaf(a, b0.x, acc2[i][0]);
                acc2[i][1] = fmaf(a, b0.y, acc2[i][1]);
                acc2[i][2] = fmaf(a, b0.z, acc2[i][2]);
                acc2[i][3] = fmaf(a, b0.w, acc2[i][3]);
                acc2[i][4] = fmaf(a, b1v.x, acc2[i][4]);
                acc2[i][5] = fmaf(a, b1v.y, acc2[i][5]);
                acc2[i][6] = fmaf(a, b1v.z, acc2[i][6]);
                acc2[i][7] = fmaf(a, b1v.w, acc2[i][7]);
            }
        }
    }

    // step 4: v = h1 + ff -> LN2 -> out.  Reuse Tsh front as padded V buffer.
    __syncthreads();
    float* Vsh = Tsh;  // 32*132 region
#pragma unroll
    for (int i = 0; i < 2; i++)
#pragma unroll
        for (int j = 0; j < 8; j++) {
            int r = tr * 2 + i, c = tc * 8 + j;
            Vsh[r * 132 + c] = H1sh[r * 132 + c] + acc2[i][j];
        }
    __syncthreads();
    for (int r = wid; r < 32; r += 8) {
        const int c0 = lane * 4;
        float v0 = Vsh[r * 132 + c0 + 0], v1 = Vsh[r * 132 + c0 + 1];
        float v2 = Vsh[r * 132 + c0 + 2], v3 = Vsh[r * 132 + c0 + 3];
        float s = v0 + v1 + v2 + v3;
#pragma unroll
        for (int o = 16; o; o >>= 1) s += __shfl_xor_sync(0xffffffffu, s, o);
        float mu = s * (1.f / 128.f);
        float d0 = v0 - mu, d1 = v1 - mu, d2 = v2 - mu, d3 = v3 - mu;
        float q = d0 * d0 + d1 * d1 + d2 * d2 + d3 * d3;
#pragma unroll
        for (int o = 16; o; o >>= 1) q += __shfl_xor_sync(0xffffffffu, q, o);
        float rs = rsqrtf(q * (1.f / 128.f) + 1e-5f);
        float4 o4;
        o4.x = d0 * rs * g2[c0 + 0] + b2[c0 + 0];
        o4.y = d1 * rs * g2[c0 + 1] + b2[c0 + 1];
        o4.z = d2 * rs * g2[c0 + 2] + b2[c0 + 2];
        o4.w = d3 * rs * g2[c0 + 3] + b2[c0 + 3];
        *(float4*)&out[(size_t)(m0 + r) * NH + c0] = o4;
    }
}

// ---------------------------------------------------------------------------
extern "C" void kernel_launch(void* const* d_in, const int* in_sizes, int n_in,
                              void* d_out, int out_size) {
    const float* node_h   = (const float*)d_in[0];
    const float* edge_h   = (const float*)d_in[1];
    const int*   edge_idx = (const int*)d_in[2];
    const float* seq_emb  = (const float*)d_in[3];
    const float* ar_mask  = (const float*)d_in[4];
    const float* mW1 = (const float*)d_in[5];
    const float* mb1 = (const float*)d_in[6];
    const float* mW2 = (const float*)d_in[7];
    const float* mb2 = (const float*)d_in[8];
    const float* mW3 = (const float*)d_in[9];
    const float* mb3 = (const float*)d_in[10];
    const float* fW1 = (const float*)d_in[11];
    const float* fb1 = (const float*)d_in[12];
    const float* fW2 = (const float*)d_in[13];
    const float* fb2 = (const float*)d_in[14];
    const float* g1  = (const float*)d_in[15];
    const float* b1  = (const float*)d_in[16];
    const float* g2  = (const float*)d_in[17];
    const float* b2  = (const float*)d_in[18];
    float* out = (float*)d_out;

    int dev = 0;
    cudaGetDevice(&dev);
    int nsm = 148;
    cudaDeviceGetAttribute(&nsm, cudaDevAttrMultiProcessorCount, dev);

    const size_t smem1 = (size_t)(16384 + 64 * 132) * sizeof(float);            // ~97 KB
    const size_t smem2 = (size_t)(16384 + 16384 + 96 * 132 + 256) * sizeof(float); // ~178.5 KB
    const size_t smem3 = (size_t)(32 * 132 + 32 * 516 + 16384) * sizeof(float);  // ~145 KB

    cudaFuncSetAttribute(k1_pre, cudaFuncAttributeMaxDynamicSharedMemorySize, (int)smem1);
    cudaFuncSetAttribute(k2_msg, cudaFuncAttributeMaxDynamicSharedMemorySize, (int)smem2);
    cudaFuncSetAttribute(k3_ff,  cudaFuncAttributeMaxDynamicSharedMemorySize, (int)smem3);

    dim3 grid1(NRES / 64, 3);
    k1_pre<<<grid1, 256, smem1>>>(node_h, seq_emb, mW1);

    k2_msg<<<nsm, 256, smem2>>>(edge_h, edge_idx, ar_mask,
                                mW1, mb1, mW2, mb2, mW3, mb3, NRES / 2);

    k3_ff<<<NRES / 32, 256, smem3>>>(node_h, fW1, fb1, fW2, fb2,
                                     g1, b1, g2, b2, out);
}